// round 8
// baseline (speedup 1.0000x reference)
#include <cuda_runtime.h>

// Batched Viterbi decode: B=1024 sequences, T=1024 steps, K=48 tags.
// Output layout (float32): [0, B) = path scores, [B, B + B*T) = best paths.

namespace {
constexpr int Bn = 1024;
constexpr int Tn = 1024;
constexpr int Kn = 48;
constexpr int START_TAG = 46;   // no transition INTO start
constexpr float NEGV = -10000.0f;

constexpr int SUBS = 2;                    // sequences per block
constexpr int NTHREADS = SUBS * Kn;        // 96 threads, all lanes useful
constexpr int SMEM_BPTR = SUBS * Tn * Kn;  // 98304 B: backpointers (u8)
constexpr int SMEM_FV   = 2 * SUBS * Kn * (int)sizeof(float);  // 768 B: double-buffered fv
constexpr int SMEM_PATH = SUBS * Tn;       // 2048 B: decoded path (u8)
constexpr int SMEM_TOTAL = SMEM_BPTR + SMEM_FV + SMEM_PATH;    // 101120 B
}

__global__ __launch_bounds__(NTHREADS) void viterbi_kernel(
    const float* __restrict__ feats,   // [B, T, K]
    const float* __restrict__ trans,   // [K, K]  trans[next][prev]
    float* __restrict__ out)           // [B] scores ++ [B*T] paths (as f32)
{
    extern __shared__ unsigned char smem[];
    unsigned char* bptr   = smem;                                       // [SUBS][T][K]
    float*         fvbuf  = reinterpret_cast<float*>(smem + SMEM_BPTR); // [2][SUBS][K]
    unsigned char* pathsh = smem + SMEM_BPTR + SMEM_FV;                 // [SUBS][T]

    const int tid = threadIdx.x;
    const int sub = tid / Kn;           // which sequence within block
    const int j   = tid - sub * Kn;     // next-tag owned by this thread
    const int b   = blockIdx.x * SUBS + sub;

    // Transition row for my next-tag, resident in registers.
    float tr[Kn];
#pragma unroll
    for (int p = 0; p < Kn; ++p) tr[p] = trans[j * Kn + p];

    // init forward variable (buffer 0)
    fvbuf[sub * Kn + j] = (j == START_TAG) ? 0.0f : NEGV;
    __syncthreads();

    const float* fb = feats + (size_t)b * Tn * Kn;
    unsigned char* bp_sub = bptr + sub * Tn * Kn;

    for (int t = 0; t < Tn; ++t) {
        const int rbuf = t & 1;
        // issue emission load early; consumed after the reduction
        const float feat = __ldg(fb + (size_t)t * Kn + j);

        // pull fv into registers via vectorized broadcast loads
        const float4* fvv =
            reinterpret_cast<const float4*>(fvbuf + rbuf * (SUBS * Kn) + sub * Kn);
        float fvreg[Kn];
#pragma unroll
        for (int i = 0; i < Kn / 4; ++i) {
            float4 v = fvv[i];
            fvreg[4 * i + 0] = v.x; fvreg[4 * i + 1] = v.y;
            fvreg[4 * i + 2] = v.z; fvreg[4 * i + 3] = v.w;
        }

        // 4 independent max/argmax chains (ILP), strict > keeps first index
        float bv0 = fvreg[0] + tr[0], bv1 = fvreg[1] + tr[1];
        float bv2 = fvreg[2] + tr[2], bv3 = fvreg[3] + tr[3];
        int bp0 = 0, bp1 = 1, bp2 = 2, bp3 = 3;
#pragma unroll
        for (int p = 4; p < Kn; p += 4) {
            float s0 = fvreg[p + 0] + tr[p + 0]; if (s0 > bv0) { bv0 = s0; bp0 = p + 0; }
            float s1 = fvreg[p + 1] + tr[p + 1]; if (s1 > bv1) { bv1 = s1; bp1 = p + 1; }
            float s2 = fvreg[p + 2] + tr[p + 2]; if (s2 > bv2) { bv2 = s2; bp2 = p + 2; }
            float s3 = fvreg[p + 3] + tr[p + 3]; if (s3 > bv3) { bv3 = s3; bp3 = p + 3; }
        }
        // merge chains; on exact value tie the SMALLER index wins (jnp.argmax)
        float bestv = bv0; int bestp = bp0;
        if (bv1 > bestv || (bv1 == bestv && bp1 < bestp)) { bestv = bv1; bestp = bp1; }
        if (bv2 > bestv || (bv2 == bestv && bp2 < bestp)) { bestv = bv2; bestp = bp2; }
        if (bv3 > bestv || (bv3 == bestv && bp3 < bestp)) { bestv = bv3; bestp = bp3; }

        bp_sub[t * Kn + j] = (unsigned char)bestp;
        fvbuf[(rbuf ^ 1) * (SUBS * Kn) + sub * Kn + j] = bestv + feat;
        __syncthreads();
    }

    // ---- terminal + backtrack ----
    // After T=1024 steps the final fv lives in buffer 0.
    // Thread j==K-1 of each sub already holds trans[STOP][*] in tr[].
    if (j == Kn - 1) {
        const float* fvf = fvbuf + sub * Kn;  // buffer 0
        float bestv = fvf[0] + tr[0]; int best = 0;
#pragma unroll
        for (int k = 1; k < Kn; ++k) {
            float s = fvf[k] + tr[k];
            if (s > bestv) { bestv = s; best = k; }
        }
        out[b] = bestv;

        int tag = best;
        for (int t = Tn - 1; t >= 0; --t) {
            pathsh[sub * Tn + t] = (unsigned char)tag;
            tag = (int)bp_sub[t * Kn + tag];
        }
    }
    __syncthreads();

    // cooperative, coalesced path writeback (int -> f32 exact)
    float* out_paths = out + Bn;
    for (int idx = tid; idx < SUBS * Tn; idx += NTHREADS) {
        int s2 = idx / Tn;
        int t  = idx - s2 * Tn;
        int bb = blockIdx.x * SUBS + s2;
        out_paths[(size_t)bb * Tn + t] = (float)pathsh[idx];
    }
}

extern "C" void kernel_launch(void* const* d_in, const int* in_sizes, int n_in,
                              void* d_out, int out_size) {
    (void)n_in; (void)out_size;
    const float* feats = (const float*)d_in[0];
    const float* trans = (const float*)d_in[1];
    // defensive: metadata order is (feats, transitions); swap if sizes say otherwise
    if (in_sizes[0] == Kn * Kn && in_sizes[1] != Kn * Kn) {
        const float* tmp = feats; feats = trans; trans = tmp;
    }
    float* out = (float*)d_out;

    cudaFuncSetAttribute(viterbi_kernel,
                         cudaFuncAttributeMaxDynamicSharedMemorySize, SMEM_TOTAL);
    viterbi_kernel<<<Bn / SUBS, NTHREADS, SMEM_TOTAL>>>(feats, trans, out);
}

// round 10
// speedup vs baseline: 1.1041x; 1.1041x over previous
#include <cuda_runtime.h>

// Batched Viterbi decode: B=1024 sequences, T=1024 steps, K=48 tags.
// Output layout (float32): [0, B) = path scores, [B, B + B*T) = best paths.
//
// R8 restructure: backpointers live in a 48MB __device__ global (fits L2)
// instead of shared memory -> smem/block drops 101KB -> 768B, so all 512
// forward blocks are resident in one wave (12 warps/SM vs 6). Backtrack is
// a separate latency-optimized kernel with L1 prefetch of upcoming rows.

namespace {
constexpr int Bn = 1024;
constexpr int Tn = 1024;
constexpr int Kn = 48;
constexpr int START_TAG = 46;
constexpr float NEGV = -10000.0f;

constexpr int SUBS = 2;              // sequences per block
constexpr int NTHREADS = SUBS * Kn;  // 96 threads
}

// Scratch (static device globals are allowed; no allocation APIs).
__device__ unsigned char g_bptr[(size_t)Bn * Tn * Kn];  // 48 MB backpointers
__device__ int g_btag[Bn];                              // terminal best tag

__global__ __launch_bounds__(NTHREADS) void viterbi_fwd(
    const float* __restrict__ feats,   // [B, T, K]
    const float* __restrict__ trans,   // [K, K]  trans[next][prev]
    float* __restrict__ out)           // [B] scores (paths filled by bwd)
{
    __shared__ __align__(16) float fvbuf[2][SUBS][Kn];

    const int tid = threadIdx.x;
    const int sub = tid / Kn;
    const int j   = tid - sub * Kn;    // next-tag owned by this thread
    const int b   = blockIdx.x * SUBS + sub;

    // Transition row for my next-tag, in registers.
    float tr[Kn];
#pragma unroll
    for (int p = 0; p < Kn; ++p) tr[p] = trans[j * Kn + p];

    fvbuf[0][sub][j] = (j == START_TAG) ? 0.0f : NEGV;
    __syncthreads();

    const float* fb = feats + (size_t)b * Tn * Kn;
    unsigned char* bp_seq = g_bptr + (size_t)b * Tn * Kn;

    // depth-2 register pipeline for the emission loads (hide DRAM latency)
    float f0 = __ldg(fb + j);
    float f1 = __ldg(fb + Kn + j);

    for (int t = 0; t < Tn; ++t) {
        const int rbuf = t & 1;
        const float feat = f0;
        f0 = f1;
        const int tn = (t + 2 < Tn) ? (t + 2) : (Tn - 1);
        f1 = __ldg(fb + (size_t)tn * Kn + j);

        // pull fv into registers via vectorized broadcast loads
        const float4* fvv = reinterpret_cast<const float4*>(&fvbuf[rbuf][sub][0]);
        float fvreg[Kn];
#pragma unroll
        for (int i = 0; i < Kn / 4; ++i) {
            float4 v = fvv[i];
            fvreg[4 * i + 0] = v.x; fvreg[4 * i + 1] = v.y;
            fvreg[4 * i + 2] = v.z; fvreg[4 * i + 3] = v.w;
        }

        // 4 independent max/argmax chains; strict > keeps first index
        float bv0 = fvreg[0] + tr[0], bv1 = fvreg[1] + tr[1];
        float bv2 = fvreg[2] + tr[2], bv3 = fvreg[3] + tr[3];
        int bp0 = 0, bp1 = 1, bp2 = 2, bp3 = 3;
#pragma unroll
        for (int p = 4; p < Kn; p += 4) {
            float s0 = fvreg[p + 0] + tr[p + 0]; if (s0 > bv0) { bv0 = s0; bp0 = p + 0; }
            float s1 = fvreg[p + 1] + tr[p + 1]; if (s1 > bv1) { bv1 = s1; bp1 = p + 1; }
            float s2 = fvreg[p + 2] + tr[p + 2]; if (s2 > bv2) { bv2 = s2; bp2 = p + 2; }
            float s3 = fvreg[p + 3] + tr[p + 3]; if (s3 > bv3) { bv3 = s3; bp3 = p + 3; }
        }
        // merge; on exact value tie the SMALLER index wins (jnp.argmax)
        float bestv = bv0; int bestp = bp0;
        if (bv1 > bestv || (bv1 == bestv && bp1 < bestp)) { bestv = bv1; bestp = bp1; }
        if (bv2 > bestv || (bv2 == bestv && bp2 < bestp)) { bestv = bv2; bestp = bp2; }
        if (bv3 > bestv || (bv3 == bestv && bp3 < bestp)) { bestv = bv3; bestp = bp3; }

        bp_seq[(size_t)t * Kn + j] = (unsigned char)bestp;
        fvbuf[rbuf ^ 1][sub][j] = bestv + feat;
        __syncthreads();
    }

    // terminal: thread j == K-1 (== STOP row) already holds trans[STOP][*]
    if (j == Kn - 1) {
        const float* fvf = &fvbuf[0][sub][0];  // last write went to buffer 0
        float bestv = fvf[0] + tr[0]; int best = 0;
#pragma unroll
        for (int k = 1; k < Kn; ++k) {
            float s = fvf[k] + tr[k];
            if (s > bestv) { bestv = s; best = k; }
        }
        out[b] = bestv;
        g_btag[b] = best;
    }
}

__global__ __launch_bounds__(32) void viterbi_bwd(float* __restrict__ out)
{
    const int b = blockIdx.x * blockDim.x + threadIdx.x;
    if (b >= Bn) return;

    const unsigned char* base = g_bptr + (size_t)b * Tn * Kn;
    float* op = out + Bn + (size_t)b * Tn;
    int tag = g_btag[b];

    constexpr int PF = 16;  // prefetch distance in rows (48B each)
    // warm up: prefetch the last PF rows so the first chases hit L1
#pragma unroll
    for (int r = 1; r <= PF; ++r) {
        const unsigned char* p = base + (size_t)(Tn - r) * Kn;
        asm volatile("prefetch.global.L1 [%0];" :: "l"(p));
    }

    for (int t = Tn - 1; t >= 0; --t) {
        op[t] = (float)tag;                       // path[t] = carry
        tag = base[(size_t)t * Kn + tag];         // carry = bptr[t][carry]
        if (t >= PF) {
            const unsigned char* p = base + (size_t)(t - PF) * Kn;
            asm volatile("prefetch.global.L1 [%0];" :: "l"(p));
        }
    }
}

extern "C" void kernel_launch(void* const* d_in, const int* in_sizes, int n_in,
                              void* d_out, int out_size) {
    (void)n_in; (void)out_size;
    const float* feats = (const float*)d_in[0];
    const float* trans = (const float*)d_in[1];
    if (in_sizes[0] == Kn * Kn && in_sizes[1] != Kn * Kn) {
        const float* tmp = feats; feats = trans; trans = tmp;
    }
    float* out = (float*)d_out;

    viterbi_fwd<<<Bn / SUBS, NTHREADS>>>(feats, trans, out);
    viterbi_bwd<<<(Bn + 31) / 32, 32>>>(out);
}

// round 11
// speedup vs baseline: 1.8154x; 1.6443x over previous
#include <cuda_runtime.h>

// Batched Viterbi decode: B=1024 sequences, T=1024 steps, K=48 tags.
// Output layout (float32): [0, B) = path scores, [B, B + B*T) = best paths.
//
// R10: (a) backtrack replaced by chunked function-composition (two fully
// parallel kernels, no long dependent-load chain); (b) forward uses packed
// add.rn.f32x2 (bit-identical, half the FADD instructions).

namespace {
constexpr int Bn = 1024;
constexpr int Tn = 1024;
constexpr int Kn = 48;
constexpr int START_TAG = 46;
constexpr float NEGV = -10000.0f;

constexpr int SUBS = 2;              // sequences per forward block
constexpr int NTHREADS = SUBS * Kn;  // 96 threads

constexpr int CH  = 64;              // backtrack chunk length
constexpr int NCH = Tn / CH;         // 16 chunks per sequence
}

// Scratch (__device__ globals: allowed; no allocation APIs).
__device__ __align__(16) unsigned char g_bptr[(size_t)Bn * Tn * Kn]; // 48 MB
__device__ unsigned char g_M[(size_t)Bn * NCH * Kn];                 // 768 KB composed maps
__device__ int g_btag[Bn];                                           // terminal best tag

// packed f32x2 add: two independent IEEE rn adds in one instruction
__device__ __forceinline__ void fadd2(unsigned long long a, unsigned long long b,
                                      float& lo, float& hi) {
    unsigned long long s;
    asm("add.rn.f32x2 %0, %1, %2;" : "=l"(s) : "l"(a), "l"(b));
    asm("mov.b64 {%0, %1}, %2;" : "=f"(lo), "=f"(hi) : "l"(s));
}

__global__ __launch_bounds__(NTHREADS) void viterbi_fwd(
    const float* __restrict__ feats,   // [B, T, K]
    const float* __restrict__ trans,   // [K, K]  trans[next][prev]
    float* __restrict__ out)           // [B] scores (paths filled later)
{
    __shared__ __align__(16) float fvbuf[2][SUBS][Kn];

    const int tid = threadIdx.x;
    const int sub = tid / Kn;
    const int j   = tid - sub * Kn;    // next-tag owned by this thread
    const int b   = blockIdx.x * SUBS + sub;

    // Transition row for my next-tag, packed into f32x2 register pairs.
    unsigned long long tr2[Kn / 2];
#pragma unroll
    for (int p = 0; p < Kn; p += 2) {
        unsigned long long lo = __float_as_uint(trans[j * Kn + p]);
        unsigned long long hi = __float_as_uint(trans[j * Kn + p + 1]);
        tr2[p / 2] = lo | (hi << 32);
    }

    fvbuf[0][sub][j] = (j == START_TAG) ? 0.0f : NEGV;
    __syncthreads();

    const float* fb = feats + (size_t)b * Tn * Kn;
    unsigned char* bp_seq = g_bptr + (size_t)b * Tn * Kn;

    // depth-2 register pipeline for the emission loads
    float f0 = __ldg(fb + j);
    float f1 = __ldg(fb + Kn + j);

    for (int t = 0; t < Tn; ++t) {
        const int rbuf = t & 1;
        const float feat = f0;
        f0 = f1;
        const int tn = (t + 2 < Tn) ? (t + 2) : (Tn - 1);
        f1 = __ldg(fb + (size_t)tn * Kn + j);

        // pull fv into registers as packed pairs (LDS.128)
        const ulonglong2* fvv =
            reinterpret_cast<const ulonglong2*>(&fvbuf[rbuf][sub][0]);
        unsigned long long fvp[Kn / 2];
#pragma unroll
        for (int i = 0; i < Kn / 4; ++i) {
            ulonglong2 v = fvv[i];
            fvp[2 * i] = v.x; fvp[2 * i + 1] = v.y;
        }

        // 4 independent max/argmax chains; strict > keeps first index
        float s0, s1, s2, s3;
        fadd2(fvp[0], tr2[0], s0, s1);
        fadd2(fvp[1], tr2[1], s2, s3);
        float bv0 = s0, bv1 = s1, bv2 = s2, bv3 = s3;
        int bp0 = 0, bp1 = 1, bp2 = 2, bp3 = 3;
#pragma unroll
        for (int g = 1; g < Kn / 4; ++g) {
            const int p = 4 * g;
            fadd2(fvp[2 * g],     tr2[2 * g],     s0, s1);
            fadd2(fvp[2 * g + 1], tr2[2 * g + 1], s2, s3);
            if (s0 > bv0) { bv0 = s0; bp0 = p;     }
            if (s1 > bv1) { bv1 = s1; bp1 = p + 1; }
            if (s2 > bv2) { bv2 = s2; bp2 = p + 2; }
            if (s3 > bv3) { bv3 = s3; bp3 = p + 3; }
        }
        // merge; on exact value tie the SMALLER index wins (jnp.argmax)
        float bestv = bv0; int bestp = bp0;
        if (bv1 > bestv || (bv1 == bestv && bp1 < bestp)) { bestv = bv1; bestp = bp1; }
        if (bv2 > bestv || (bv2 == bestv && bp2 < bestp)) { bestv = bv2; bestp = bp2; }
        if (bv3 > bestv || (bv3 == bestv && bp3 < bestp)) { bestv = bv3; bestp = bp3; }

        bp_seq[(size_t)t * Kn + j] = (unsigned char)bestp;
        fvbuf[rbuf ^ 1][sub][j] = bestv + feat;
        __syncthreads();
    }

    // terminal: thread j == K-1 (== STOP row)
    if (j == Kn - 1) {
        const float* fvf = &fvbuf[0][sub][0];  // last write went to buffer 0
        float bestv = fvf[0] + __ldg(trans + (Kn - 1) * Kn);
        int best = 0;
#pragma unroll
        for (int k = 1; k < Kn; ++k) {
            float s = fvf[k] + __ldg(trans + (Kn - 1) * Kn + k);
            if (s > bestv) { bestv = s; best = k; }
        }
        out[b] = bestv;
        g_btag[b] = best;
    }
}

// ---- Phase B: per (seq, chunk), compose the backpointer maps ----
// M[b][c][k] = carry after walking chunk c backward starting with carry k.
__global__ __launch_bounds__(64) void viterbi_compose()
{
    const int b = blockIdx.x >> 4;        // / NCH
    const int c = blockIdx.x & (NCH - 1);
    const int tid = threadIdx.x;

    __shared__ __align__(16) unsigned char rows[CH * Kn];  // 3072 B

    const uint4* src = reinterpret_cast<const uint4*>(
        g_bptr + ((size_t)b * Tn + (size_t)c * CH) * Kn);
    uint4* dst = reinterpret_cast<uint4*>(rows);
#pragma unroll
    for (int i = tid; i < CH * Kn / 16; i += 64) dst[i] = src[i];
    __syncthreads();

    if (tid < Kn) {
        int tag = tid;
#pragma unroll 4
        for (int t = CH - 1; t >= 0; --t) tag = rows[t * Kn + tag];
        g_M[((size_t)b * NCH + c) * Kn + tid] = (unsigned char)tag;
    }
}

// ---- Phase D: per (seq, chunk), compose suffix maps -> entry tag, replay ----
__global__ __launch_bounds__(64) void viterbi_replay(float* __restrict__ out)
{
    const int b = blockIdx.x >> 4;
    const int c = blockIdx.x & (NCH - 1);
    const int tid = threadIdx.x;

    __shared__ __align__(16) unsigned char rows[CH * Kn];
    __shared__ int s_end;

    const uint4* src = reinterpret_cast<const uint4*>(
        g_bptr + ((size_t)b * Tn + (size_t)c * CH) * Kn);
    uint4* dst = reinterpret_cast<uint4*>(rows);
#pragma unroll
    for (int i = tid; i < CH * Kn / 16; i += 64) dst[i] = src[i];

    if (tid == 0) {
        int tag = g_btag[b];
        for (int cc = NCH - 1; cc > c; --cc)
            tag = g_M[((size_t)b * NCH + cc) * Kn + tag];
        s_end = tag;
    }
    __syncthreads();

    if (tid == 0) {
        int tag = s_end;
        float* op = out + Bn + (size_t)b * Tn + (size_t)c * CH;
#pragma unroll 4
        for (int t = CH - 1; t >= 0; --t) {
            op[t] = (float)tag;            // path[t] = carry
            tag = rows[t * Kn + tag];      // carry = bptr[t][carry]
        }
    }
}

extern "C" void kernel_launch(void* const* d_in, const int* in_sizes, int n_in,
                              void* d_out, int out_size) {
    (void)n_in; (void)out_size;
    const float* feats = (const float*)d_in[0];
    const float* trans = (const float*)d_in[1];
    if (in_sizes[0] == Kn * Kn && in_sizes[1] != Kn * Kn) {
        const float* tmp = feats; feats = trans; trans = tmp;
    }
    float* out = (float*)d_out;

    viterbi_fwd<<<Bn / SUBS, NTHREADS>>>(feats, trans, out);
    viterbi_compose<<<Bn * NCH, 64>>>();
    viterbi_replay<<<Bn * NCH, 64>>>(out);
}